// round 12
// baseline (speedup 1.0000x reference)
#include <cuda_runtime.h>
#include <cuda_bf16.h>

// Problem constants
#define BATCH 512
#define SEQ   200
#define BS    (BATCH*SEQ)   // 102400
#define TT    10
#define EMB   25
#define HID   64
#define C3    192           // 3*HID

// ---------------- scratch (device globals: no allocation allowed) ----------
__device__ float g_x[BS * EMB];                  // mean-pooled embeddings
__device__ float g_mask[BS];                     // step mask as float 0/1
__device__ float g_xp[2ull * BS * C3];           // x projections (fp32)
__device__ float g_rnn[(size_t)BS * 128];        // concat(hs_f, hs_b)
__device__ float g_hT[BATCH * HID];              // final forward hidden
__device__ float g_e[BS];                        // attention logits

#define XPD ((size_t)BS * C3)

// ---------------- helpers --------------------------------------------------
union F2U { float2 f; unsigned long long u; };

static __device__ __forceinline__ float2 ffma2f(float2 a, float2 b, float2 c) {
    F2U A, B, C, D; A.f = a; B.f = b; C.f = c;
    asm("fma.rn.f32x2 %0, %1, %2, %3;" : "=l"(D.u) : "l"(A.u), "l"(B.u), "l"(C.u));
    return D.f;
}

static __device__ __forceinline__ float sigm_f(float x) {
    return __fdividef(1.0f, 1.0f + __expf(-x));
}
static __device__ __forceinline__ float tanh_f(float x) {
    float e = __expf(2.0f * x);
    return 1.0f - __fdividef(2.0f, e + 1.0f);
}

// ---------------- K1: embedding mean + step mask ---------------------------
__global__ __launch_bounds__(256) void embed_kernel(
    const int* __restrict__ inp, const float* __restrict__ emb)
{
    int wid = threadIdx.x >> 5, lane = threadIdx.x & 31;
    int g = blockIdx.x * 8 + wid;               // (b,s) index
    if (g >= BS) return;
    int base = g * TT;

    int tk = 0;
    if (lane < TT) tk = inp[base + lane];
    unsigned bal = __ballot_sync(0xffffffffu, (lane < TT) && (tk != 0));
    int cnt = __popc(bal);

    float acc = 0.0f;
    #pragma unroll
    for (int t = 0; t < TT; ++t) {
        int tok = __shfl_sync(0xffffffffu, tk, t);
        if (tok != 0 && lane < EMB) acc += emb[tok * EMB + lane];
    }
    float denom = (float)(cnt > 0 ? cnt : 1);
    if (lane < EMB) g_x[g * EMB + lane] = acc / denom;
    int tok0 = __shfl_sync(0xffffffffu, tk, 0);
    if (lane == 0) g_mask[g] = (tok0 != 0) ? 1.0f : 0.0f;
}

// ---------------- K1b: x projection (both directions) ----------------------
__global__ __launch_bounds__(256) void xproj_kernel(
    const float* __restrict__ Wf, const float* __restrict__ bf,
    const float* __restrict__ Wb, const float* __restrict__ bb)
{
    __shared__ float2 Wsh[2][EMB][96];   // [dir][k][colpair]
    __shared__ float2 xsh[32][26];       // duplicated pairs {v,v}

    const int tid = threadIdx.x;
    const int base = blockIdx.x * 32;

    const float2* wf2 = (const float2*)Wf;
    const float2* wb2 = (const float2*)Wb;
    for (int i = tid; i < EMB * 96; i += 256) {
        ((float2*)Wsh)[i] = wf2[i];
        ((float2*)Wsh)[EMB * 96 + i] = wb2[i];
    }
    for (int i = tid; i < 32 * EMB; i += 256) {
        float v = g_x[(size_t)base * EMB + i];
        xsh[i / EMB][i % EMB] = make_float2(v, v);
    }
    __syncthreads();

    const int w = tid >> 5, lane = tid & 31, c0 = 2 * lane;

    float2 bf0 = *(const float2*)&bf[c0];
    float2 bf1 = *(const float2*)&bf[64 + c0];
    float2 bf2v = *(const float2*)&bf[128 + c0];
    float2 bb0 = *(const float2*)&bb[c0];
    float2 bb1 = *(const float2*)&bb[64 + c0];
    float2 bb2v = *(const float2*)&bb[128 + c0];

    float2 af[4][3], ab[4][3];
    #pragma unroll
    for (int r = 0; r < 4; ++r) {
        af[r][0] = bf0; af[r][1] = bf1; af[r][2] = bf2v;
        ab[r][0] = bb0; ab[r][1] = bb1; ab[r][2] = bb2v;
    }

    #pragma unroll 5
    for (int k = 0; k < EMB; ++k) {
        float2 wfz = Wsh[0][k][lane], wfr = Wsh[0][k][32 + lane], wfh = Wsh[0][k][64 + lane];
        float2 wbz = Wsh[1][k][lane], wbr = Wsh[1][k][32 + lane], wbh = Wsh[1][k][64 + lane];
        #pragma unroll
        for (int r = 0; r < 4; ++r) {
            float2 xv = xsh[w * 4 + r][k];
            af[r][0] = ffma2f(xv, wfz, af[r][0]);
            af[r][1] = ffma2f(xv, wfr, af[r][1]);
            af[r][2] = ffma2f(xv, wfh, af[r][2]);
            ab[r][0] = ffma2f(xv, wbz, ab[r][0]);
            ab[r][1] = ffma2f(xv, wbr, ab[r][1]);
            ab[r][2] = ffma2f(xv, wbh, ab[r][2]);
        }
    }

    #pragma unroll
    for (int r = 0; r < 4; ++r) {
        size_t g = (size_t)base + w * 4 + r;
        float* of = g_xp + g * C3;
        *(float2*)&of[c0]       = af[r][0];
        *(float2*)&of[64 + c0]  = af[r][1];
        *(float2*)&of[128 + c0] = af[r][2];
        float* ob = g_xp + XPD + g * C3;
        *(float2*)&ob[c0]       = ab[r][0];
        *(float2*)&ob[64 + c0]  = ab[r][1];
        *(float2*)&ob[128 + c0] = ab[r][2];
    }
}

// ---------------- K2: bidirectional GRU scan (register-resident U) ---------
// 128 blocks x 512 threads (16 warps). Block = (dir, 8 batch rows).
// k-split 4 x row-split 4 (2 rows per warp):
//   FMA role: warp w -> rows ((w&3)*2 .. +1), k-quarter (w>>2)*16
//   Gate role: warp w < 8 -> local row w (full 64 cols, 2 per lane),
//              reduces over 4 partials (half the smem traffic of k-split 8).
__global__ __launch_bounds__(512, 1) void gru_kernel(
    const float* __restrict__ Uf, const float* __restrict__ bf,
    const float* __restrict__ Ub, const float* __restrict__ bb)
{
    extern __shared__ float sh[];
    float2* h2   = (float2*)sh;          // [8][64] duplicated pairs {h,h}
    float2* part = h2 + 8 * 64;          // [kq 4][row 8][96 colpairs]

    const int tid = threadIdx.x;
    const int w = tid >> 5, lane = tid & 31, c0 = 2 * lane;
    const int dir = blockIdx.x >> 6;
    const int rowbase = (blockIdx.x & 63) * 8;
    const float* Um = dir ? Ub : Uf;
    const float* bm = dir ? bb : bf;

    const int rg = (w & 3) * 2;         // FMA row group (0,2,4,6)
    const int kq = w >> 2;              // k quarter (0..3), 16 k each

    // load U slice to registers: 16 k-rows x (3 gates x 2 cols) = 96 regs
    float2 Uz[16], Ur[16], Uh[16];
    #pragma unroll
    for (int k = 0; k < 16; ++k) {
        const float* up = Um + (kq * 16 + k) * C3;
        Uz[k] = *(const float2*)&up[c0];
        Ur[k] = *(const float2*)&up[64 + c0];
        Uh[k] = *(const float2*)&up[128 + c0];
    }

    // gate-role state (warps 0..7 only)
    const int grow = rowbase + (w & 7);
    float2 b1z = make_float2(0.f, 0.f), b1r = b1z, b1h = b1z;
    float2 hprev = make_float2(0.f, 0.f);
    float2 xz = hprev, xr = hprev, xh = hprev;
    float mk = 0.f;
    const float* xpbase = g_xp + (size_t)dir * XPD + (size_t)grow * SEQ * C3;

    if (w < 8) {
        b1z = *(const float2*)&bm[192 + c0];
        b1r = *(const float2*)&bm[256 + c0];
        b1h = *(const float2*)&bm[320 + c0];
        h2[w * 64 + lane]      = make_float2(0.f, 0.f);
        h2[w * 64 + 32 + lane] = make_float2(0.f, 0.f);
        // prefetch xp + mask for t=0
        int s0 = dir ? (SEQ - 1) : 0;
        const float* xp0 = xpbase + (size_t)s0 * C3;
        xz = *(const float2*)&xp0[c0];
        xr = *(const float2*)&xp0[64 + c0];
        xh = *(const float2*)&xp0[128 + c0];
        mk = g_mask[grow * SEQ + s0];
    }
    __syncthreads();

    for (int t = 0; t < SEQ; ++t) {
        int s = dir ? (SEQ - 1 - t) : t;

        // ---- FMA phase: partial h @ U for 2 rows over this warp's 16 k ----
        float2 az0 = make_float2(0.f, 0.f), ar0 = az0, ah0 = az0;
        float2 az1 = az0, ar1 = az0, ah1 = az0;
        #pragma unroll
        for (int k = 0; k < 16; k += 2) {
            float4 p0 = *(const float4*)&h2[(rg + 0) * 64 + kq * 16 + k];
            float4 p1 = *(const float4*)&h2[(rg + 1) * 64 + kq * 16 + k];
            float2 a0 = make_float2(p0.x, p0.y), b0 = make_float2(p0.z, p0.w);
            float2 a1 = make_float2(p1.x, p1.y), b1 = make_float2(p1.z, p1.w);
            az0 = ffma2f(a0, Uz[k], az0); az0 = ffma2f(b0, Uz[k+1], az0);
            ar0 = ffma2f(a0, Ur[k], ar0); ar0 = ffma2f(b0, Ur[k+1], ar0);
            ah0 = ffma2f(a0, Uh[k], ah0); ah0 = ffma2f(b0, Uh[k+1], ah0);
            az1 = ffma2f(a1, Uz[k], az1); az1 = ffma2f(b1, Uz[k+1], az1);
            ar1 = ffma2f(a1, Ur[k], ar1); ar1 = ffma2f(b1, Ur[k+1], ar1);
            ah1 = ffma2f(a1, Uh[k], ah1); ah1 = ffma2f(b1, Uh[k+1], ah1);
        }
        {
            float2* pp0 = part + ((size_t)(kq * 8 + rg + 0)) * 96;
            pp0[lane]      = az0;
            pp0[32 + lane] = ar0;
            pp0[64 + lane] = ah0;
            float2* pp1 = part + ((size_t)(kq * 8 + rg + 1)) * 96;
            pp1[lane]      = az1;
            pp1[32 + lane] = ar1;
            pp1[64 + lane] = ah1;
        }
        __syncthreads();

        // ---- gate phase: warp w (<8) handles local row w ----
        if (w < 8) {
            float2 pz = make_float2(0.f, 0.f), pr = pz, ph = pz;
            #pragma unroll
            for (int q = 0; q < 4; ++q) {
                const float2* pp = part + ((size_t)(q * 8 + w)) * 96;
                float2 a = pp[lane], b = pp[32 + lane], c = pp[64 + lane];
                pz.x += a.x; pz.y += a.y;
                pr.x += b.x; pr.y += b.y;
                ph.x += c.x; ph.y += c.y;
            }
            float zx = sigm_f(xz.x + pz.x + b1z.x);
            float zy = sigm_f(xz.y + pz.y + b1z.y);
            float rx = sigm_f(xr.x + pr.x + b1r.x);
            float ry = sigm_f(xr.y + pr.y + b1r.y);
            float hhx = tanh_f(xh.x + rx * (ph.x + b1h.x));
            float hhy = tanh_f(xh.y + ry * (ph.y + b1h.y));
            float hnx = hhx + zx * (hprev.x - hhx);
            float hny = hhy + zy * (hprev.y - hhy);
            hnx = hprev.x + mk * (hnx - hprev.x);
            hny = hprev.y + mk * (hny - hprev.y);
            hprev = make_float2(hnx, hny);

            *(float4*)&h2[w * 64 + c0] = make_float4(hnx, hnx, hny, hny);
            *(float2*)&g_rnn[((size_t)grow * SEQ + s) * 128 + dir * 64 + c0] = hprev;

            if (t < SEQ - 1) {
                int sn = dir ? (SEQ - 2 - t) : (t + 1);
                const float* xpn = xpbase + (size_t)sn * C3;
                xz = *(const float2*)&xpn[c0];
                xr = *(const float2*)&xpn[64 + c0];
                xh = *(const float2*)&xpn[128 + c0];
                mk = g_mask[grow * SEQ + sn];
            }
        }
        __syncthreads();
    }

    if (dir == 0 && w < 8) *(float2*)&g_hT[grow * HID + c0] = hprev;
}

// ---------------- K3a: attention logits (software-pipelined staging) -------
// grid 2048 = 512 batches x 4 seq-chunks of 50 steps. block 256 = 8 warps,
// 8-way k-split with register-resident duplicated Wk; transposed staging.
// Tile t+1's g_rnn reads are issued right after tile t's staging barrier so
// their L2 latency hides under tile t's compute + reduce.
#define STILE 10
#define SPITCH 14
__global__ __launch_bounds__(256) void attn_logits_kernel(
    const float* __restrict__ Wk, const float* __restrict__ bk,
    const float* __restrict__ Wq, const float* __restrict__ bq,
    const float* __restrict__ We, const float* __restrict__ be)
{
    __shared__ float ostT[128 * SPITCH];           // 7 KB
    __shared__ float4 part[8][STILE/2][32];        // 20 KB
    __shared__ float q_sh[64];

    const int b = blockIdx.x >> 2;
    const int sbase = (blockIdx.x & 3) * 50;
    const int tid = threadIdx.x;
    const int lane = tid & 31, w = tid >> 5;

    // staging index mapping for this thread: 5 elements, idx = tid + 256*i
    int sst[5], skk[5];
    #pragma unroll
    for (int i = 0; i < 5; ++i) {
        int idx = tid + 256 * i;
        sst[i] = idx >> 7;           // step within tile (0..9)
        skk[i] = idx & 127;          // k (0..127)
    }

    const float* orow_base = g_rnn + (size_t)b * SEQ * 128;

    // prologue: load tile 0 staging values into registers
    float v[5];
    #pragma unroll
    for (int i = 0; i < 5; ++i)
        v[i] = orow_base[(size_t)(sbase + sst[i]) * 128 + skk[i]];

    // Wk duplicated pairs in registers: k in [16w, 16w+16), cols lane & lane+32
    float2 WkA[16], WkB[16];
    #pragma unroll
    for (int k = 0; k < 16; ++k) {
        float a = Wk[(16 * w + k) * 64 + lane];
        float c = Wk[(16 * w + k) * 64 + 32 + lane];
        WkA[k] = make_float2(a, a);
        WkB[k] = make_float2(c, c);
    }

    if (tid < 64) {
        float acc = bq[tid];
        #pragma unroll 8
        for (int k = 0; k < HID; ++k) acc += g_hT[b * HID + k] * Wq[k * 64 + tid];
        q_sh[tid] = acc;
    }
    __syncthreads();

    const float bkA = bk[lane],      bkB = bk[32 + lane];
    const float qA  = q_sh[lane],    qB  = q_sh[32 + lane];
    const float WeA = We[lane],      WeB = We[32 + lane];
    const float beb = be[0];

    #pragma unroll 1
    for (int tile = 0; tile < 5; ++tile) {
        const int st = sbase + tile * STILE;

        // stage current tile from registers (transposed)
        #pragma unroll
        for (int i = 0; i < 5; ++i)
            ostT[skk[i] * SPITCH + sst[i]] = v[i];
        __syncthreads();

        // prefetch next tile (latency hides under compute + reduce below)
        if (tile < 4) {
            #pragma unroll
            for (int i = 0; i < 5; ++i)
                v[i] = orow_base[(size_t)(st + STILE + sst[i]) * 128 + skk[i]];
        }

        // compute: warp w covers k in [16w,16w+16); step pairs r
        #pragma unroll
        for (int r = 0; r < STILE / 2; ++r) {
            float2 aA = make_float2(0.f, 0.f), aB = make_float2(0.f, 0.f);
            #pragma unroll
            for (int k = 0; k < 16; ++k) {
                float2 o2 = *(const float2*)&ostT[(16 * w + k) * SPITCH + 2 * r];
                aA = ffma2f(o2, WkA[k], aA);
                aB = ffma2f(o2, WkB[k], aB);
            }
            part[w][r][lane] = make_float4(aA.x, aA.y, aB.x, aB.y);
        }
        __syncthreads();

        // reduce: warp w (<5) handles step pair r=w
        if (w < STILE / 2) {
            float4 s4 = make_float4(0.f, 0.f, 0.f, 0.f);
            #pragma unroll
            for (int q = 0; q < 8; ++q) {
                float4 p = part[q][w][lane];
                s4.x += p.x; s4.y += p.y; s4.z += p.z; s4.w += p.w;
            }
            float e0 = tanh_f(s4.x + bkA + qA) * WeA + tanh_f(s4.z + bkB + qB) * WeB;
            float e1 = tanh_f(s4.y + bkA + qA) * WeA + tanh_f(s4.w + bkB + qB) * WeB;
            #pragma unroll
            for (int off = 16; off; off >>= 1) {
                e0 += __shfl_xor_sync(0xffffffffu, e0, off);
                e1 += __shfl_xor_sync(0xffffffffu, e1, off);
            }
            if (lane == 0) {
                int st0 = st + 2 * w;
                float m0 = g_mask[b * SEQ + st0];
                float m1 = g_mask[b * SEQ + st0 + 1];
                g_e[b * SEQ + st0]     = e0 + beb + (1.0f - m0) * (-1e9f);
                g_e[b * SEQ + st0 + 1] = e1 + beb + (1.0f - m1) * (-1e9f);
            }
        }
        __syncthreads();
    }
}

// ---------------- K3b: softmax + weighted sum -------------------------------
__global__ __launch_bounds__(256) void attn_final_kernel(float* __restrict__ out)
{
    __shared__ float e_sh[SEQ];
    __shared__ float red[256];

    const int b = blockIdx.x;
    const int tid = threadIdx.x;

    if (tid < SEQ) e_sh[tid] = g_e[b * SEQ + tid];
    __syncthreads();

    // softmax over S
    red[tid] = (tid < SEQ) ? e_sh[tid] : -3.4e38f;
    __syncthreads();
    for (int o = 128; o; o >>= 1) {
        if (tid < o) red[tid] = fmaxf(red[tid], red[tid + o]);
        __syncthreads();
    }
    float maxv = red[0];
    __syncthreads();
    float wv = (tid < SEQ) ? __expf(e_sh[tid] - maxv) : 0.0f;
    red[tid] = wv;
    __syncthreads();
    for (int o = 128; o; o >>= 1) {
        if (tid < o) red[tid] += red[tid + o];
        __syncthreads();
    }
    float tot = red[0];
    __syncthreads();
    if (tid < SEQ) e_sh[tid] = __fdividef(wv, tot);
    __syncthreads();

    // weighted sum
    int j = tid & 127, half = tid >> 7;
    float acc = 0.0f;
    const float* orow = g_rnn + (size_t)b * SEQ * 128 + j;
    for (int s2 = half * 100; s2 < half * 100 + 100; ++s2)
        acc += e_sh[s2] * orow[(size_t)s2 * 128];
    red[tid] = acc;
    __syncthreads();
    if (tid < 128) out[b * 128 + tid] = red[tid] + red[tid + 128];
}

// ---------------- launch ----------------------------------------------------
extern "C" void kernel_launch(void* const* d_in, const int* in_sizes, int n_in,
                              void* d_out, int out_size)
{
    const int*   inp = (const int*)d_in[0];
    const float* emb = (const float*)d_in[1];
    const float* Wf  = (const float*)d_in[2];
    const float* Uf  = (const float*)d_in[3];
    const float* bf  = (const float*)d_in[4];
    const float* Wb  = (const float*)d_in[5];
    const float* Ub  = (const float*)d_in[6];
    const float* bb  = (const float*)d_in[7];
    const float* Wk  = (const float*)d_in[8];
    const float* bk  = (const float*)d_in[9];
    const float* Wq  = (const float*)d_in[10];
    const float* bq  = (const float*)d_in[11];
    const float* We  = (const float*)d_in[12];
    const float* be  = (const float*)d_in[13];
    float* out = (float*)d_out;

    const int gru_smem = (8 * 64 + 4 * 8 * 96) * 8;   // h2 + part, 28672 B
    cudaFuncSetAttribute(gru_kernel, cudaFuncAttributeMaxDynamicSharedMemorySize, gru_smem);

    embed_kernel<<<BS / 8, 256>>>(inp, emb);
    xproj_kernel<<<BS / 32, 256>>>(Wf, bf, Wb, bb);
    gru_kernel<<<128, 512, gru_smem>>>(Uf, bf, Ub, bb);
    attn_logits_kernel<<<BATCH * 4, 256>>>(Wk, bk, Wq, bq, We, be);
    attn_final_kernel<<<BATCH, 256>>>(out);
}

// round 16
// speedup vs baseline: 1.1167x; 1.1167x over previous
#include <cuda_runtime.h>
#include <cuda_bf16.h>

// Problem constants
#define BATCH 512
#define SEQ   200
#define BS    (BATCH*SEQ)   // 102400
#define TT    10
#define EMB   25
#define HID   64
#define C3    192           // 3*HID
#define GR    7             // batch rows per GRU block
#define GBLK  74            // GRU blocks per direction (74*7=518 >= 512)

// ---------------- scratch (device globals: no allocation allowed) ----------
__device__ float g_x[BS * EMB];                  // mean-pooled embeddings
__device__ float g_mask[BS];                     // step mask as float 0/1
__device__ float g_xp[2ull * BS * C3];           // x projections (fp32)
__device__ float g_rnn[(size_t)BS * 128];        // concat(hs_f, hs_b)
__device__ float g_hT[BATCH * HID];              // final forward hidden
__device__ float g_e[BS];                        // attention logits

#define XPD ((size_t)BS * C3)

// ---------------- helpers --------------------------------------------------
union F2U { float2 f; unsigned long long u; };

static __device__ __forceinline__ float2 ffma2f(float2 a, float2 b, float2 c) {
    F2U A, B, C, D; A.f = a; B.f = b; C.f = c;
    asm("fma.rn.f32x2 %0, %1, %2, %3;" : "=l"(D.u) : "l"(A.u), "l"(B.u), "l"(C.u));
    return D.f;
}

static __device__ __forceinline__ float sigm_f(float x) {
    return __fdividef(1.0f, 1.0f + __expf(-x));
}
static __device__ __forceinline__ float tanh_f(float x) {
    float e = __expf(2.0f * x);
    return 1.0f - __fdividef(2.0f, e + 1.0f);
}

// ---------------- K1: embedding mean + step mask ---------------------------
__global__ __launch_bounds__(256) void embed_kernel(
    const int* __restrict__ inp, const float* __restrict__ emb)
{
    int wid = threadIdx.x >> 5, lane = threadIdx.x & 31;
    int g = blockIdx.x * 8 + wid;               // (b,s) index
    if (g >= BS) return;
    int base = g * TT;

    int tk = 0;
    if (lane < TT) tk = inp[base + lane];
    unsigned bal = __ballot_sync(0xffffffffu, (lane < TT) && (tk != 0));
    int cnt = __popc(bal);

    float acc = 0.0f;
    #pragma unroll
    for (int t = 0; t < TT; ++t) {
        int tok = __shfl_sync(0xffffffffu, tk, t);
        if (tok != 0 && lane < EMB) acc += emb[tok * EMB + lane];
    }
    float denom = (float)(cnt > 0 ? cnt : 1);
    if (lane < EMB) g_x[g * EMB + lane] = acc / denom;
    int tok0 = __shfl_sync(0xffffffffu, tk, 0);
    if (lane == 0) g_mask[g] = (tok0 != 0) ? 1.0f : 0.0f;
}

// ---------------- K1b: x projection (both directions) ----------------------
__global__ __launch_bounds__(256) void xproj_kernel(
    const float* __restrict__ Wf, const float* __restrict__ bf,
    const float* __restrict__ Wb, const float* __restrict__ bb)
{
    __shared__ float2 Wsh[2][EMB][96];   // [dir][k][colpair]
    __shared__ float2 xsh[32][26];       // duplicated pairs {v,v}

    const int tid = threadIdx.x;
    const int base = blockIdx.x * 32;

    const float2* wf2 = (const float2*)Wf;
    const float2* wb2 = (const float2*)Wb;
    for (int i = tid; i < EMB * 96; i += 256) {
        ((float2*)Wsh)[i] = wf2[i];
        ((float2*)Wsh)[EMB * 96 + i] = wb2[i];
    }
    for (int i = tid; i < 32 * EMB; i += 256) {
        float v = g_x[(size_t)base * EMB + i];
        xsh[i / EMB][i % EMB] = make_float2(v, v);
    }
    __syncthreads();

    const int w = tid >> 5, lane = tid & 31, c0 = 2 * lane;

    float2 bf0 = *(const float2*)&bf[c0];
    float2 bf1 = *(const float2*)&bf[64 + c0];
    float2 bf2v = *(const float2*)&bf[128 + c0];
    float2 bb0 = *(const float2*)&bb[c0];
    float2 bb1 = *(const float2*)&bb[64 + c0];
    float2 bb2v = *(const float2*)&bb[128 + c0];

    float2 af[4][3], ab[4][3];
    #pragma unroll
    for (int r = 0; r < 4; ++r) {
        af[r][0] = bf0; af[r][1] = bf1; af[r][2] = bf2v;
        ab[r][0] = bb0; ab[r][1] = bb1; ab[r][2] = bb2v;
    }

    #pragma unroll 5
    for (int k = 0; k < EMB; ++k) {
        float2 wfz = Wsh[0][k][lane], wfr = Wsh[0][k][32 + lane], wfh = Wsh[0][k][64 + lane];
        float2 wbz = Wsh[1][k][lane], wbr = Wsh[1][k][32 + lane], wbh = Wsh[1][k][64 + lane];
        #pragma unroll
        for (int r = 0; r < 4; ++r) {
            float2 xv = xsh[w * 4 + r][k];
            af[r][0] = ffma2f(xv, wfz, af[r][0]);
            af[r][1] = ffma2f(xv, wfr, af[r][1]);
            af[r][2] = ffma2f(xv, wfh, af[r][2]);
            ab[r][0] = ffma2f(xv, wbz, ab[r][0]);
            ab[r][1] = ffma2f(xv, wbr, ab[r][1]);
            ab[r][2] = ffma2f(xv, wbh, ab[r][2]);
        }
    }

    #pragma unroll
    for (int r = 0; r < 4; ++r) {
        size_t g = (size_t)base + w * 4 + r;
        float* of = g_xp + g * C3;
        *(float2*)&of[c0]       = af[r][0];
        *(float2*)&of[64 + c0]  = af[r][1];
        *(float2*)&of[128 + c0] = af[r][2];
        float* ob = g_xp + XPD + g * C3;
        *(float2*)&ob[c0]       = ab[r][0];
        *(float2*)&ob[64 + c0]  = ab[r][1];
        *(float2*)&ob[128 + c0] = ab[r][2];
    }
}

// ---------------- K2: bidirectional GRU scan (register-resident U) ---------
// 148 blocks x 512 threads = 2 dirs x 74 blocks x 7 rows (all SMs busy,
// per-SM rows 8 -> 7). Same per-row math/reduction order as the r7 kernel.
//   FMA role: warps 0-7  -> rows 0-3, k-eighth w
//             warps 8-15 -> rows 4-6, k-eighth w-8   (balanced per SMSP)
//   Gate role: warp w < 7 -> local row w (full 64 cols, 2 per lane)
template<int NR>
static __device__ __forceinline__ void gru_fma_phase(
    const float2* __restrict__ h2, float2* __restrict__ part,
    int rg, int kq, int lane,
    const float2* Uz, const float2* Ur, const float2* Uh)
{
    float2 az[NR], ar[NR], ah[NR];
    #pragma unroll
    for (int r = 0; r < NR; ++r) {
        az[r] = make_float2(0.f, 0.f);
        ar[r] = make_float2(0.f, 0.f);
        ah[r] = make_float2(0.f, 0.f);
    }
    #pragma unroll
    for (int k = 0; k < 8; k += 2) {
        #pragma unroll
        for (int r = 0; r < NR; ++r) {
            float4 p = *(const float4*)&h2[(rg + r) * 64 + kq * 8 + k];
            float2 a = make_float2(p.x, p.y), b = make_float2(p.z, p.w);
            az[r] = ffma2f(a, Uz[k], az[r]); az[r] = ffma2f(b, Uz[k + 1], az[r]);
            ar[r] = ffma2f(a, Ur[k], ar[r]); ar[r] = ffma2f(b, Ur[k + 1], ar[r]);
            ah[r] = ffma2f(a, Uh[k], ah[r]); ah[r] = ffma2f(b, Uh[k + 1], ah[r]);
        }
    }
    #pragma unroll
    for (int r = 0; r < NR; ++r) {
        float2* pp = part + ((size_t)(kq * GR + rg + r)) * 96;
        pp[lane]      = az[r];
        pp[32 + lane] = ar[r];
        pp[64 + lane] = ah[r];
    }
}

__global__ __launch_bounds__(512, 1) void gru_kernel(
    const float* __restrict__ Uf, const float* __restrict__ bf,
    const float* __restrict__ Ub, const float* __restrict__ bb)
{
    extern __shared__ float sh[];
    float2* h2   = (float2*)sh;          // [GR][64] duplicated pairs {h,h}
    float2* part = h2 + GR * 64;         // [kq 8][row GR][96 colpairs]

    const int tid = threadIdx.x;
    const int w = tid >> 5, lane = tid & 31, c0 = 2 * lane;
    const int dir = (blockIdx.x >= GBLK) ? 1 : 0;
    const int rowbase = (dir ? blockIdx.x - GBLK : blockIdx.x) * GR;
    const float* Um = dir ? Ub : Uf;
    const float* bm = dir ? bb : bf;

    const int kq = w & 7;               // k eighth (0..7)

    // load U slice to registers: 8 k-rows x (3 gates x 2 cols)
    float2 Uz[8], Ur[8], Uh[8];
    #pragma unroll
    for (int k = 0; k < 8; ++k) {
        const float* up = Um + (kq * 8 + k) * C3;
        Uz[k] = *(const float2*)&up[c0];
        Ur[k] = *(const float2*)&up[64 + c0];
        Uh[k] = *(const float2*)&up[128 + c0];
    }

    // gate-role state (warps 0..6 only)
    const int grow = rowbase + w;                  // valid only for w < GR
    const bool gvalid = (w < GR) && (grow < BATCH);
    float2 b1z = make_float2(0.f, 0.f), b1r = b1z, b1h = b1z;
    float2 hprev = make_float2(0.f, 0.f);
    float2 xz = hprev, xr = hprev, xh = hprev;
    float mk = 0.f;
    const float* xpbase = g_xp + (size_t)dir * XPD + (size_t)(gvalid ? grow : 0) * SEQ * C3;

    if (w < GR) {
        b1z = *(const float2*)&bm[192 + c0];
        b1r = *(const float2*)&bm[256 + c0];
        b1h = *(const float2*)&bm[320 + c0];
    }
    if (tid < GR * 64) h2[tid] = make_float2(0.f, 0.f);
    if (gvalid) {
        // prefetch xp + mask for t=0
        int s0 = dir ? (SEQ - 1) : 0;
        const float* xp0 = xpbase + (size_t)s0 * C3;
        xz = *(const float2*)&xp0[c0];
        xr = *(const float2*)&xp0[64 + c0];
        xh = *(const float2*)&xp0[128 + c0];
        mk = g_mask[grow * SEQ + s0];
    }
    __syncthreads();

    for (int t = 0; t < SEQ; ++t) {
        int s = dir ? (SEQ - 1 - t) : t;

        // ---- FMA phase ----
        if (w < 8) gru_fma_phase<4>(h2, part, 0, kq, lane, Uz, Ur, Uh);
        else       gru_fma_phase<3>(h2, part, 4, kq, lane, Uz, Ur, Uh);
        __syncthreads();

        // ---- gate phase: warp w (<GR) handles local row w ----
        if (w < GR) {
            float2 pz = make_float2(0.f, 0.f), pr = pz, ph = pz;
            #pragma unroll
            for (int q = 0; q < 8; ++q) {
                const float2* pp = part + ((size_t)(q * GR + w)) * 96;
                float2 a = pp[lane], b = pp[32 + lane], c = pp[64 + lane];
                pz.x += a.x; pz.y += a.y;
                pr.x += b.x; pr.y += b.y;
                ph.x += c.x; ph.y += c.y;
            }
            float zx = sigm_f(xz.x + pz.x + b1z.x);
            float zy = sigm_f(xz.y + pz.y + b1z.y);
            float rx = sigm_f(xr.x + pr.x + b1r.x);
            float ry = sigm_f(xr.y + pr.y + b1r.y);
            float hhx = tanh_f(xh.x + rx * (ph.x + b1h.x));
            float hhy = tanh_f(xh.y + ry * (ph.y + b1h.y));
            float hnx = hhx + zx * (hprev.x - hhx);
            float hny = hhy + zy * (hprev.y - hhy);
            hnx = hprev.x + mk * (hnx - hprev.x);
            hny = hprev.y + mk * (hny - hprev.y);
            hprev = make_float2(hnx, hny);

            *(float4*)&h2[w * 64 + c0] = make_float4(hnx, hnx, hny, hny);
            if (gvalid)
                *(float2*)&g_rnn[((size_t)grow * SEQ + s) * 128 + dir * 64 + c0] = hprev;

            if (gvalid && t < SEQ - 1) {
                int sn = dir ? (SEQ - 2 - t) : (t + 1);
                const float* xpn = xpbase + (size_t)sn * C3;
                xz = *(const float2*)&xpn[c0];
                xr = *(const float2*)&xpn[64 + c0];
                xh = *(const float2*)&xpn[128 + c0];
                mk = g_mask[grow * SEQ + sn];
            }
        }
        __syncthreads();
    }

    if (dir == 0 && gvalid) *(float2*)&g_hT[grow * HID + c0] = hprev;
}

// ---------------- K3a: attention logits (software-pipelined staging) -------
// grid 2048 = 512 batches x 4 seq-chunks of 50 steps. block 256 = 8 warps,
// 8-way k-split with register-resident duplicated Wk; transposed staging.
// Tile t+1's g_rnn reads are issued right after tile t's staging barrier so
// their L2 latency hides under tile t's compute + reduce.
#define STILE 10
#define SPITCH 14
__global__ __launch_bounds__(256) void attn_logits_kernel(
    const float* __restrict__ Wk, const float* __restrict__ bk,
    const float* __restrict__ Wq, const float* __restrict__ bq,
    const float* __restrict__ We, const float* __restrict__ be)
{
    __shared__ float ostT[128 * SPITCH];           // 7 KB
    __shared__ float4 part[8][STILE/2][32];        // 20 KB
    __shared__ float q_sh[64];

    const int b = blockIdx.x >> 2;
    const int sbase = (blockIdx.x & 3) * 50;
    const int tid = threadIdx.x;
    const int lane = tid & 31, w = tid >> 5;

    // staging index mapping for this thread: 5 elements, idx = tid + 256*i
    int sst[5], skk[5];
    #pragma unroll
    for (int i = 0; i < 5; ++i) {
        int idx = tid + 256 * i;
        sst[i] = idx >> 7;           // step within tile (0..9)
        skk[i] = idx & 127;          // k (0..127)
    }

    const float* orow_base = g_rnn + (size_t)b * SEQ * 128;

    // prologue: load tile 0 staging values into registers
    float v[5];
    #pragma unroll
    for (int i = 0; i < 5; ++i)
        v[i] = orow_base[(size_t)(sbase + sst[i]) * 128 + skk[i]];

    // Wk duplicated pairs in registers: k in [16w, 16w+16), cols lane & lane+32
    float2 WkA[16], WkB[16];
    #pragma unroll
    for (int k = 0; k < 16; ++k) {
        float a = Wk[(16 * w + k) * 64 + lane];
        float c = Wk[(16 * w + k) * 64 + 32 + lane];
        WkA[k] = make_float2(a, a);
        WkB[k] = make_float2(c, c);
    }

    if (tid < 64) {
        float acc = bq[tid];
        #pragma unroll 8
        for (int k = 0; k < HID; ++k) acc += g_hT[b * HID + k] * Wq[k * 64 + tid];
        q_sh[tid] = acc;
    }
    __syncthreads();

    const float bkA = bk[lane],      bkB = bk[32 + lane];
    const float qA  = q_sh[lane],    qB  = q_sh[32 + lane];
    const float WeA = We[lane],      WeB = We[32 + lane];
    const float beb = be[0];

    #pragma unroll 1
    for (int tile = 0; tile < 5; ++tile) {
        const int st = sbase + tile * STILE;

        // stage current tile from registers (transposed)
        #pragma unroll
        for (int i = 0; i < 5; ++i)
            ostT[skk[i] * SPITCH + sst[i]] = v[i];
        __syncthreads();

        // prefetch next tile (latency hides under compute + reduce below)
        if (tile < 4) {
            #pragma unroll
            for (int i = 0; i < 5; ++i)
                v[i] = orow_base[(size_t)(st + STILE + sst[i]) * 128 + skk[i]];
        }

        // compute: warp w covers k in [16w,16w+16); step pairs r
        #pragma unroll
        for (int r = 0; r < STILE / 2; ++r) {
            float2 aA = make_float2(0.f, 0.f), aB = make_float2(0.f, 0.f);
            #pragma unroll
            for (int k = 0; k < 16; ++k) {
                float2 o2 = *(const float2*)&ostT[(16 * w + k) * SPITCH + 2 * r];
                aA = ffma2f(o2, WkA[k], aA);
                aB = ffma2f(o2, WkB[k], aB);
            }
            part[w][r][lane] = make_float4(aA.x, aA.y, aB.x, aB.y);
        }
        __syncthreads();

        // reduce: warp w (<5) handles step pair r=w
        if (w < STILE / 2) {
            float4 s4 = make_float4(0.f, 0.f, 0.f, 0.f);
            #pragma unroll
            for (int q = 0; q < 8; ++q) {
                float4 p = part[q][w][lane];
                s4.x += p.x; s4.y += p.y; s4.z += p.z; s4.w += p.w;
            }
            float e0 = tanh_f(s4.x + bkA + qA) * WeA + tanh_f(s4.z + bkB + qB) * WeB;
            float e1 = tanh_f(s4.y + bkA + qA) * WeA + tanh_f(s4.w + bkB + qB) * WeB;
            #pragma unroll
            for (int off = 16; off; off >>= 1) {
                e0 += __shfl_xor_sync(0xffffffffu, e0, off);
                e1 += __shfl_xor_sync(0xffffffffu, e1, off);
            }
            if (lane == 0) {
                int st0 = st + 2 * w;
                float m0 = g_mask[b * SEQ + st0];
                float m1 = g_mask[b * SEQ + st0 + 1];
                g_e[b * SEQ + st0]     = e0 + beb + (1.0f - m0) * (-1e9f);
                g_e[b * SEQ + st0 + 1] = e1 + beb + (1.0f - m1) * (-1e9f);
            }
        }
        __syncthreads();
    }
}

// ---------------- K3b: softmax + weighted sum -------------------------------
__global__ __launch_bounds__(256) void attn_final_kernel(float* __restrict__ out)
{
    __shared__ float e_sh[SEQ];
    __shared__ float red[256];

    const int b = blockIdx.x;
    const int tid = threadIdx.x;

    if (tid < SEQ) e_sh[tid] = g_e[b * SEQ + tid];
    __syncthreads();

    // softmax over S
    red[tid] = (tid < SEQ) ? e_sh[tid] : -3.4e38f;
    __syncthreads();
    for (int o = 128; o; o >>= 1) {
        if (tid < o) red[tid] = fmaxf(red[tid], red[tid + o]);
        __syncthreads();
    }
    float maxv = red[0];
    __syncthreads();
    float wv = (tid < SEQ) ? __expf(e_sh[tid] - maxv) : 0.0f;
    red[tid] = wv;
    __syncthreads();
    for (int o = 128; o; o >>= 1) {
        if (tid < o) red[tid] += red[tid + o];
        __syncthreads();
    }
    float tot = red[0];
    __syncthreads();
    if (tid < SEQ) e_sh[tid] = __fdividef(wv, tot);
    __syncthreads();

    // weighted sum
    int j = tid & 127, half = tid >> 7;
    float acc = 0.0f;
    const float* orow = g_rnn + (size_t)b * SEQ * 128 + j;
    for (int s2 = half * 100; s2 < half * 100 + 100; ++s2)
        acc += e_sh[s2] * orow[(size_t)s2 * 128];
    red[tid] = acc;
    __syncthreads();
    if (tid < 128) out[b * 128 + tid] = red[tid] + red[tid + 128];
}

// ---------------- launch ----------------------------------------------------
extern "C" void kernel_launch(void* const* d_in, const int* in_sizes, int n_in,
                              void* d_out, int out_size)
{
    const int*   inp = (const int*)d_in[0];
    const float* emb = (const float*)d_in[1];
    const float* Wf  = (const float*)d_in[2];
    const float* Uf  = (const float*)d_in[3];
    const float* bf  = (const float*)d_in[4];
    const float* Wb  = (const float*)d_in[5];
    const float* Ub  = (const float*)d_in[6];
    const float* bb  = (const float*)d_in[7];
    const float* Wk  = (const float*)d_in[8];
    const float* bk  = (const float*)d_in[9];
    const float* Wq  = (const float*)d_in[10];
    const float* bq  = (const float*)d_in[11];
    const float* We  = (const float*)d_in[12];
    const float* be  = (const float*)d_in[13];
    float* out = (float*)d_out;

    const int gru_smem = (GR * 64 + 8 * GR * 96) * 8;   // h2 + part, 46592 B
    cudaFuncSetAttribute(gru_kernel, cudaFuncAttributeMaxDynamicSharedMemorySize, gru_smem);

    embed_kernel<<<BS / 8, 256>>>(inp, emb);
    xproj_kernel<<<BS / 32, 256>>>(Wf, bf, Wb, bb);
    gru_kernel<<<2 * GBLK, 512, gru_smem>>>(Uf, bf, Ub, bb);
    attn_logits_kernel<<<BATCH * 4, 256>>>(Wk, bk, Wq, bq, We, be);
    attn_final_kernel<<<BATCH, 256>>>(out);
}